// round 17
// baseline (speedup 1.0000x reference)
#include <cuda_runtime.h>
#include <cuda_bf16.h>
#include <cstdint>

// MissHitScatter: inputs [N=65536, D=1024] f32 -> out [P=4, N, D] f32.
// slice 0 = copy of input, slices 1..3 = zeros. 1.25 GiB total traffic.
//
// R16: champion structure (contiguous 32 KB per-block spans, pure block
// types, batched __ldg MLP=8 + __stwt streaming stores, independent blocks)
// with the PHASE ORDER flipped: zero chunks run first (blockIdx 0..24575),
// copy chunks last (blockIdx 24576..32767). The read stream then overlaps
// the write-queue drain of the pure-write phase instead of competing with
// the kernel ramp. Per-warp address streams are byte-identical to champion.

#define V 8  // float4 per thread; block span = 256*V float4 = 32 KB

__global__ void __launch_bounds__(256) misshit_scatter_kernel(
    const float4* __restrict__ in, float4* __restrict__ out,
    size_t n4, unsigned n_zero_blocks)
{
    const size_t span = (size_t)blockDim.x * V;
    const float4 z = make_float4(0.f, 0.f, 0.f, 0.f);

    if (blockIdx.x < n_zero_blocks) {
        // Zero chunk k = blockIdx.x: contiguous span in slices 1..3.
        size_t base = n4 + (size_t)blockIdx.x * span + threadIdx.x;
#pragma unroll
        for (int j = 0; j < V; j++)
            __stwt(out + base + (size_t)j * blockDim.x, z);
    } else {
        // Copy chunk c = blockIdx.x - n_zero_blocks: contiguous span, slice 0.
        size_t base = (size_t)(blockIdx.x - n_zero_blocks) * span + threadIdx.x;
        float4 v[V];
#pragma unroll
        for (int j = 0; j < V; j++)
            v[j] = __ldg(in + base + (size_t)j * blockDim.x);
#pragma unroll
        for (int j = 0; j < V; j++)
            __stwt(out + base + (size_t)j * blockDim.x, v[j]);
    }
}

extern "C" void kernel_launch(void* const* d_in, const int* in_sizes, int n_in,
                              void* d_out, int out_size) {
    const size_t n_elems = (size_t)in_sizes[0];   // 65536 * 1024 floats
    const size_t n4 = n_elems / 4;                // 16Mi float4 per slice

    const int threads = 256;
    const size_t span = (size_t)threads * V;      // 2048 float4 = 32 KB
    // Shape guarantees exact divisibility (16Mi % 2048 == 0).
    const unsigned copy_blocks = (unsigned)(n4 / span);        // 8192
    const unsigned zero_blocks = 3 * copy_blocks;              // 24576
    const unsigned blocks = copy_blocks + zero_blocks;         // 32768

    misshit_scatter_kernel<<<blocks, threads>>>(
        (const float4*)d_in[0], (float4*)d_out, n4, zero_blocks);
}